// round 3
// baseline (speedup 1.0000x reference)
#include <cuda_runtime.h>
#include <cstdint>

#define BATCH 4
#define NPTS 8192
#define KNN 16
#define NP_TOTAL (BATCH * NPTS)   // 32768

typedef unsigned long long ull;

// Layouts (point-major, feat first, xyz last):
//   g_fcat1: [p][256 feat | 3 xyz | 1 pad]  stride 260
//   g_fcat2: [p][128 feat | 3 xyz | 1 pad]  stride 132
// Lt matrices are permuted to match (xyz channels moved to the end).
__device__ float g_fcat1[NP_TOTAL * 260];
__device__ float g_fcat2[NP_TOTAL * 132];
__device__ float g_f2[NP_TOTAL * 128];
__device__ float g_Lt1[2072 * 128];
__device__ float g_Lt2[1048 * 128];
__device__ float g_w1t[128 * 128];
__device__ float g_w2t[128 * 64];

__device__ __forceinline__ float lrelu(float v) { return v >= 0.f ? v : 0.1f * v; }

__device__ __forceinline__ ull ffma2(ull a, ull b, ull c) {
    ull d;
    asm("fma.rn.f32x2 %0, %1, %2, %3;" : "=l"(d) : "l"(a), "l"(b), "l"(c));
    return d;
}
__device__ __forceinline__ ull dup2(float x) {
    ull d;
    asm("mov.b64 %0, {%1, %1};" : "=l"(d) : "f"(x));
    return d;
}
__device__ __forceinline__ float2 unpk(ull v) {
    float2 r;
    asm("mov.b64 {%0, %1}, %2;" : "=f"(r.x), "=f"(r.y) : "l"(v));
    return r;
}

// ---------------- prep kernels -----------------------------------------------
__global__ void prep_weights(const float* __restrict__ wl1, const float* __restrict__ wl2,
                             const float* __restrict__ wm1, const float* __restrict__ wm2) {
    int i = blockIdx.x * blockDim.x + threadIdx.x;
    if (i < 2072 * 128) {
        int f_new = i >> 7, o = i & 127;
        int c_new = f_new >> 3, m = f_new & 7;
        int c_orig = (c_new < 256) ? c_new + 3 : c_new - 256;
        g_Lt1[i] = wl1[o * 2072 + c_orig * 8 + m];
    }
    if (i < 1048 * 128) {
        int f_new = i >> 7, o = i & 127;
        int c_new = f_new >> 3, m = f_new & 7;
        int c_orig = (c_new < 128) ? c_new + 3 : c_new - 128;
        g_Lt2[i] = wl2[o * 1048 + c_orig * 8 + m];
    }
    if (i < 128 * 128) { int c = i >> 7, o = i & 127; g_w1t[i] = wm1[o * 128 + c]; }
    if (i < 128 * 64)  { int o = i >> 6, j = i & 63;  g_w2t[i] = wm2[j * 128 + o]; }
}

__global__ void prep_xyz(const float* __restrict__ xyz) {
    int i = blockIdx.x * blockDim.x + threadIdx.x;
    if (i >= NP_TOTAL * 3) return;
    int p = i / 3, d = i - p * 3;
    int b = p >> 13, n = p & (NPTS - 1);
    float v = xyz[((size_t)b * 3 + d) * NPTS + n];
    g_fcat1[(size_t)p * 260 + 256 + d] = v;
    g_fcat2[(size_t)p * 132 + 128 + d] = v;
}

// feat [B,256,N] -> g_fcat1[p][c]
__global__ void transpose_feat(const float* __restrict__ feat) {
    __shared__ float tile[32][33];
    int b = blockIdx.z;
    int n0 = blockIdx.x * 32, c0 = blockIdx.y * 32;
    int x = threadIdx.x, y = threadIdx.y;
    tile[y][x] = feat[((size_t)b * 256 + c0 + y) * NPTS + n0 + x];
    __syncthreads();
    g_fcat1[((size_t)(b * NPTS + n0 + y)) * 260 + c0 + x] = tile[x][y];
}

// ---------------- fused point-conv --------------------------------------------
// CTA: 256 threads, 32 points. Chunks of 66 channels (528 f) of agg in smem.
// GEMM: thread = (ptg = tid&15 -> pts {ptg, ptg+16}) x (og = tid>>4 -> o-sets
// {og*4..+3} and {og*4+64..+67}), packed f32x2 accumulators.
template <int CIN, int STRIDE_IN, int OUT_STRIDE>
__global__ void __launch_bounds__(256, 2)
conv_kernel(const float* __restrict__ fcat, const int* __restrict__ knn,
            const float* __restrict__ w_wn, const float* __restrict__ b_wn,
            const float* __restrict__ Lt, const float* __restrict__ b_lin,
            float* __restrict__ out) {
    constexpr int CIN3 = CIN + 3;
    constexpr int ASTRIDE = 532;          // 4*133, 133 odd -> conflict-free LDS
    constexpr int CHUNK_C = 66;           // 528 f per chunk
    constexpr int FBLK = 48;              // Lt staging block

    extern __shared__ float sm[];
    float* s_agg = sm;                    // 32*532
    float* s_w   = sm + 32 * ASTRIDE;     // 32*16*8 = 4096
    float* s_lt  = s_w + 4096;            // 48*128 = 6144

    __shared__ int   s_nbr[32 * 16];
    __shared__ float s_cx[32 * 3];
    __shared__ float s_wn[24];
    __shared__ float s_bwn[8];

    const int tid  = threadIdx.x;
    const int base = blockIdx.x * 32;
    const int boff = (base >> 13) << 13;  // batch offset in point index

    if (tid < 24) s_wn[tid] = w_wn[tid];
    if (tid < 8)  s_bwn[tid] = b_wn[tid];
    if (tid < 96) {
        int pt = tid / 3, d = tid - pt * 3;
        s_cx[pt * 3 + d] = fcat[(size_t)(base + pt) * STRIDE_IN + CIN + d];
    }
    {
        int id = tid;
#pragma unroll
        for (int r = 0; r < 2; ++r, id += 256) {
            int pt = id >> 4, k = id & 15;
            s_nbr[id] = boff + knn[(size_t)(base + pt) * KNN + k];
        }
    }
    __syncthreads();

    // weight-net: w[pt][k][m] = leaky(w_wn @ (xyz_j - xyz_p) + b_wn)
    {
        int id = tid;
#pragma unroll
        for (int r = 0; r < 2; ++r, id += 256) {
            int pt = id >> 4, k = id & 15;
            int j = s_nbr[id];
            const float* nx = fcat + (size_t)j * STRIDE_IN + CIN;
            float px = nx[0] - s_cx[pt * 3 + 0];
            float py = nx[1] - s_cx[pt * 3 + 1];
            float pz = nx[2] - s_cx[pt * 3 + 2];
#pragma unroll
            for (int m = 0; m < 8; ++m) {
                float v = s_wn[m * 3 + 0] * px + s_wn[m * 3 + 1] * py +
                          s_wn[m * 3 + 2] * pz + s_bwn[m];
                s_w[pt * 128 + k * 8 + m] = lrelu(v);
            }
        }
    }
    __syncthreads();

    const int ptg = tid & 15;
    const int og  = tid >> 4;
    const int o0a = og * 4;
    const int o0b = og * 4 + 64;
    const int wid = tid >> 5, lane = tid & 31;

    ull acc[8];
#pragma unroll
    for (int i = 0; i < 8; ++i) acc[i] = 0ULL;

    for (int c0 = 0; c0 < CIN3; c0 += CHUNK_C) {
        const int cc = min(CHUNK_C, CIN3 - c0);

        // ---- agg build: warp wid handles points wid*4 .. wid*4+3
#pragma unroll
        for (int i = 0; i < 4; ++i) {
            const int pt = wid * 4 + i;
            const int* nb = s_nbr + pt * 16;
            const ull* wp = (const ull*)(s_w + pt * 128);
            int nbr_r[16];
#pragma unroll
            for (int k = 0; k < 16; ++k) nbr_r[k] = nb[k];
            for (int cl = lane; cl < cc; cl += 32) {
                const float* fc = fcat + c0 + cl;
                ull a0 = 0, a1 = 0, a2 = 0, a3 = 0;
#pragma unroll
                for (int k = 0; k < 16; ++k) {
                    float fv = __ldg(fc + (size_t)nbr_r[k] * STRIDE_IN);
                    ull fd = dup2(fv);
                    ulonglong2 w01 = *(const ulonglong2*)(wp + k * 4);
                    ulonglong2 w23 = *(const ulonglong2*)(wp + k * 4 + 2);
                    a0 = ffma2(fd, w01.x, a0);
                    a1 = ffma2(fd, w01.y, a1);
                    a2 = ffma2(fd, w23.x, a2);
                    a3 = ffma2(fd, w23.y, a3);
                }
                float* ap = s_agg + pt * ASTRIDE + cl * 8;
                float2 r0 = unpk(a0), r1 = unpk(a1), r2 = unpk(a2), r3 = unpk(a3);
                *(float4*)ap       = make_float4(r0.x, r0.y, r1.x, r1.y);
                *(float4*)(ap + 4) = make_float4(r2.x, r2.y, r3.x, r3.y);
            }
        }
        __syncthreads();

        // ---- GEMM over this chunk's f-range, Lt staged in 48-f blocks
        const int fc_len = cc * 8;
        const float* ltbase = Lt + (size_t)(c0 * 8) * 128;
        const float* aggA = s_agg + ptg * ASTRIDE;
        const float* aggB = s_agg + (ptg + 16) * ASTRIDE;

        for (int fb = 0; fb < fc_len; fb += FBLK) {
            const int blen = min(FBLK, fc_len - fb);
            {
                const float4* src = (const float4*)(ltbase + (size_t)fb * 128);
                float4* dst = (float4*)s_lt;
                const int n4 = blen * 32;
                for (int i = tid; i < n4; i += 256) dst[i] = __ldg(src + i);
            }
            __syncthreads();
            for (int f = 0; f < blen; f += 4) {
                float4 a4 = *(const float4*)(aggA + fb + f);
                float4 b4 = *(const float4*)(aggB + fb + f);
#pragma unroll
                for (int q = 0; q < 4; ++q) {
                    float av = (q == 0) ? a4.x : (q == 1) ? a4.y : (q == 2) ? a4.z : a4.w;
                    float bv = (q == 0) ? b4.x : (q == 1) ? b4.y : (q == 2) ? b4.z : b4.w;
                    ull ad = dup2(av), bd = dup2(bv);
                    const float* ltr = s_lt + (f + q) * 128;
                    ulonglong2 l0 = *(const ulonglong2*)(ltr + o0a);
                    ulonglong2 l1 = *(const ulonglong2*)(ltr + o0b);
                    acc[0] = ffma2(ad, l0.x, acc[0]);
                    acc[1] = ffma2(ad, l0.y, acc[1]);
                    acc[2] = ffma2(ad, l1.x, acc[2]);
                    acc[3] = ffma2(ad, l1.y, acc[3]);
                    acc[4] = ffma2(bd, l0.x, acc[4]);
                    acc[5] = ffma2(bd, l0.y, acc[5]);
                    acc[6] = ffma2(bd, l1.x, acc[6]);
                    acc[7] = ffma2(bd, l1.y, acc[7]);
                }
            }
            __syncthreads();
        }
    }

    // ---- epilogue: bias + leaky, two points, two o-quads each
    float4 bias0 = __ldg((const float4*)(b_lin + o0a));
    float4 bias1 = __ldg((const float4*)(b_lin + o0b));
#pragma unroll
    for (int h = 0; h < 2; ++h) {
        const int p = base + ptg + h * 16;
        float2 t0 = unpk(acc[h * 4 + 0]);
        float2 t1 = unpk(acc[h * 4 + 1]);
        float2 t2 = unpk(acc[h * 4 + 2]);
        float2 t3 = unpk(acc[h * 4 + 3]);
        float4 va = make_float4(lrelu(t0.x + bias0.x), lrelu(t0.y + bias0.y),
                                lrelu(t1.x + bias0.z), lrelu(t1.y + bias0.w));
        float4 vb = make_float4(lrelu(t2.x + bias1.x), lrelu(t2.y + bias1.y),
                                lrelu(t3.x + bias1.z), lrelu(t3.y + bias1.w));
        *(float4*)(out + (size_t)p * OUT_STRIDE + o0a) = va;
        *(float4*)(out + (size_t)p * OUT_STRIDE + o0b) = vb;
    }
}

// ---------------- MLP head -----------------------------------------------------
__global__ void mlp_kernel(const float* __restrict__ w_last, const float* __restrict__ b1,
                           const float* __restrict__ b2, const float* __restrict__ blast,
                           float* __restrict__ out) {
    __shared__ float s_f[16 * 128];
    __shared__ float s_h1[16 * 128];
    __shared__ float s_h2[16 * 64];
    const int tid = threadIdx.x;
    const int p0  = blockIdx.x * 16;

    for (int i = tid; i < 16 * 128; i += 256) s_f[i] = g_f2[(size_t)p0 * 128 + i];
    __syncthreads();

    {
        int o = tid & 127, tg = tid >> 7;
        float acc[8];
#pragma unroll
        for (int i = 0; i < 8; ++i) acc[i] = 0.f;
        for (int c = 0; c < 128; ++c) {
            float wv = g_w1t[c * 128 + o];
#pragma unroll
            for (int i = 0; i < 8; ++i) acc[i] += s_f[(tg * 8 + i) * 128 + c] * wv;
        }
        float bb = b1[o];
#pragma unroll
        for (int i = 0; i < 8; ++i) s_h1[(tg * 8 + i) * 128 + o] = lrelu(acc[i] + bb);
    }
    __syncthreads();

    {
        int jj = tid & 63, tg = tid >> 6;
        float acc[4];
#pragma unroll
        for (int i = 0; i < 4; ++i) acc[i] = 0.f;
        for (int c = 0; c < 128; ++c) {
            float wv = g_w2t[c * 64 + jj];
#pragma unroll
            for (int i = 0; i < 4; ++i) acc[i] += s_h1[(tg * 4 + i) * 128 + c] * wv;
        }
        float bb = b2[jj];
#pragma unroll
        for (int i = 0; i < 4; ++i) s_h2[(tg * 4 + i) * 64 + jj] = lrelu(acc[i] + bb);
    }
    __syncthreads();

    const int b = p0 >> 13, n0 = p0 & (NPTS - 1);
    for (int i = tid; i < 16 * 64; i += 256) {
        int t = i & 15, jj = i >> 4;
        out[((size_t)(b * 64 + jj)) * NPTS + n0 + t] = s_h2[t * 64 + jj];
    }
    if (tid < 48) {
        int t = tid & 15, d = tid >> 4;
        float acc = 0.f;
#pragma unroll 8
        for (int jj = 0; jj < 64; ++jj) acc += w_last[d * 64 + jj] * s_h2[t * 64 + jj];
        out[(size_t)BATCH * 64 * NPTS + ((size_t)(b * 3 + d)) * NPTS + n0 + t] = acc + blast[d];
    }
}

// ---------------- launch --------------------------------------------------------
extern "C" void kernel_launch(void* const* d_in, const int* in_sizes, int n_in,
                              void* d_out, int out_size) {
    const float* xyz    = (const float*)d_in[0];
    const float* feat   = (const float*)d_in[1];
    const int*   knn    = (const int*)d_in[2];
    const float* w_wn1  = (const float*)d_in[3];
    const float* b_wn1  = (const float*)d_in[4];
    const float* w_lin1 = (const float*)d_in[5];
    const float* b_lin1 = (const float*)d_in[6];
    const float* w_wn2  = (const float*)d_in[7];
    const float* b_wn2  = (const float*)d_in[8];
    const float* w_lin2 = (const float*)d_in[9];
    const float* b_lin2 = (const float*)d_in[10];
    const float* w_mlp1 = (const float*)d_in[11];
    const float* b_mlp1 = (const float*)d_in[12];
    const float* w_mlp2 = (const float*)d_in[13];
    const float* b_mlp2 = (const float*)d_in[14];
    const float* w_last = (const float*)d_in[15];
    const float* b_last = (const float*)d_in[16];
    float* out = (float*)d_out;

    void *p_fcat1, *p_fcat2, *p_f2, *p_Lt1, *p_Lt2;
    cudaGetSymbolAddress(&p_fcat1, g_fcat1);
    cudaGetSymbolAddress(&p_fcat2, g_fcat2);
    cudaGetSymbolAddress(&p_f2, g_f2);
    cudaGetSymbolAddress(&p_Lt1, g_Lt1);
    cudaGetSymbolAddress(&p_Lt2, g_Lt2);

    prep_weights<<<(2072 * 128 + 255) / 256, 256>>>(w_lin1, w_lin2, w_mlp1, w_mlp2);
    prep_xyz<<<(NP_TOTAL * 3 + 255) / 256, 256>>>(xyz);
    {
        dim3 tb(32, 32);
        dim3 tg(NPTS / 32, 256 / 32, BATCH);
        transpose_feat<<<tg, tb>>>(feat);
    }

    // dyn smem: (32*532 + 4096 + 48*128) * 4 = 109056 bytes
    const size_t smem = (size_t)(32 * 532 + 4096 + 48 * 128) * 4;

    cudaFuncSetAttribute(conv_kernel<256, 260, 132>,
                         cudaFuncAttributeMaxDynamicSharedMemorySize, (int)smem);
    conv_kernel<256, 260, 132><<<NP_TOTAL / 32, 256, smem>>>(
        (const float*)p_fcat1, knn, w_wn1, b_wn1, (const float*)p_Lt1, b_lin1,
        (float*)p_fcat2);

    cudaFuncSetAttribute(conv_kernel<128, 132, 128>,
                         cudaFuncAttributeMaxDynamicSharedMemorySize, (int)smem);
    conv_kernel<128, 132, 128><<<NP_TOTAL / 32, 256, smem>>>(
        (const float*)p_fcat2, knn, w_wn2, b_wn2, (const float*)p_Lt2, b_lin2,
        (float*)p_f2);

    mlp_kernel<<<NP_TOTAL / 16, 256>>>(w_last, b_mlp1, b_mlp2, b_last, out);
}

// round 5
// speedup vs baseline: 1.2865x; 1.2865x over previous
#include <cuda_runtime.h>
#include <cuda_bf16.h>
#include <cstdint>

#define BATCH 4
#define NPTS 8192
#define KNN 16
#define NP_TOTAL (BATCH * NPTS)

typedef unsigned long long ull;

#define NCH1 33   // conv1: 259 ch -> 33 chunks of 8 ch (64 f)
#define NCH2 17   // conv2: 131 ch -> 17 chunks
#define ROWW 40   // padded row stride in 32-bit words (80 bf16 = 160B)
#define CHUNK_WORDS 10240   // per-chunk B image: 2 halves x 128 rows x 40 words

__device__ float g_fcat1[NP_TOTAL * 260];   // [p][256 feat | 3 xyz | pad]
__device__ float g_fcat2[NP_TOTAL * 132];   // [p][128 feat | 3 xyz | pad]
__device__ float g_f2[NP_TOTAL * 128];
__device__ uint32_t g_B1[NCH1 * CHUNK_WORDS];  // bf16x2 words, [ci][h][n][40]
__device__ uint32_t g_B2[NCH2 * CHUNK_WORDS];
__device__ float g_w1t[128 * 128];
__device__ float g_w2t[128 * 64];

__device__ __forceinline__ float lrelu(float v) { return v >= 0.f ? v : 0.1f * v; }
__device__ __forceinline__ ull ffma2(ull a, ull b, ull c) {
    ull d; asm("fma.rn.f32x2 %0, %1, %2, %3;" : "=l"(d) : "l"(a), "l"(b), "l"(c)); return d;
}
__device__ __forceinline__ ull dup2(float x) {
    ull d; asm("mov.b64 %0, {%1, %1};" : "=l"(d) : "f"(x)); return d;
}
__device__ __forceinline__ float2 unpk(ull v) {
    float2 r; asm("mov.b64 {%0, %1}, %2;" : "=f"(r.x), "=f"(r.y) : "l"(v)); return r;
}
__device__ __forceinline__ uint32_t pack_bf16(float a, float b) {
    __nv_bfloat162 h = __floats2bfloat162_rn(a, b);
    return *(uint32_t*)&h;
}

// mma.sync m16n8k16 bf16: C += A*B.  A frag {a0,a1,a2,a3}, B {b0,b1}, C {c0..c3}
__device__ __forceinline__ void mma_bf16(float* c, uint32_t a0, uint32_t a1,
                                         uint32_t a2, uint32_t a3,
                                         uint32_t b0, uint32_t b1) {
    asm volatile(
        "mma.sync.aligned.m16n8k16.row.col.f32.bf16.bf16.f32 "
        "{%0,%1,%2,%3}, {%4,%5,%6,%7}, {%8,%9}, {%0,%1,%2,%3};"
        : "+f"(c[0]), "+f"(c[1]), "+f"(c[2]), "+f"(c[3])
        : "r"(a0), "r"(a1), "r"(a2), "r"(a3), "r"(b0), "r"(b1));
}

// ---------------- prep ----------------------------------------------------------
__global__ void prep_weights(const float* __restrict__ wm1, const float* __restrict__ wm2) {
    int i = blockIdx.x * blockDim.x + threadIdx.x;
    if (i < 128 * 128) { int c = i >> 7, o = i & 127; g_w1t[i] = wm1[o * 128 + c]; }
    if (i < 128 * 64)  { int o = i >> 6, j = i & 63;  g_w2t[i] = wm2[j * 128 + o]; }
}

__global__ void prep_xyz(const float* __restrict__ xyz) {
    int i = blockIdx.x * blockDim.x + threadIdx.x;
    if (i >= NP_TOTAL * 3) return;
    int p = i / 3, d = i - p * 3;
    int b = p >> 13, n = p & (NPTS - 1);
    float v = xyz[((size_t)b * 3 + d) * NPTS + n];
    g_fcat1[(size_t)p * 260 + 256 + d] = v;
    g_fcat2[(size_t)p * 132 + 128 + d] = v;
}

__global__ void transpose_feat(const float* __restrict__ feat) {
    __shared__ float tile[32][33];
    int b = blockIdx.z;
    int n0 = blockIdx.x * 32, c0 = blockIdx.y * 32;
    int x = threadIdx.x, y = threadIdx.y;
    tile[y][x] = feat[((size_t)b * 256 + c0 + y) * NPTS + n0 + x];
    __syncthreads();
    g_fcat1[((size_t)(b * NPTS + n0 + y)) * 260 + c0 + x] = tile[x][y];
}

// Build pre-split (bf16 hi/lo) pre-permuted B images.
// Storage col layout per k16 sub: pos(k) = (k&1) | (((k>>3)&1)<<1) | (((k>>1)&3)<<2)
__device__ __forceinline__ float fetch_w(const float* wl, int Freal, int CIN, int n,
                                         int ci, int col) {
    if (col >= 64) return 0.f;
    int s = col >> 4, pos = col & 15;
    int k = (pos & 1) | (((pos >> 2) & 3) << 1) | (((pos >> 1) & 1) << 3);
    int f = ci * 64 + s * 16 + k;
    int c = f >> 3, m = f & 7;
    if (c >= CIN + 3) return 0.f;
    int co = (c < CIN) ? c + 3 : c - CIN;
    return wl[n * Freal + co * 8 + m];
}

__global__ void prep_B(const float* __restrict__ wl1, const float* __restrict__ wl2) {
    int i = blockIdx.x * blockDim.x + threadIdx.x;
    if (i < NCH1 * CHUNK_WORDS) {
        int ci = i / CHUNK_WORDS, r = i % CHUNK_WORDS;
        int h = r / 5120, r2 = r % 5120;
        int n = r2 / ROWW, wc = r2 % ROWW;
        float v0 = fetch_w(wl1, 2072, 256, n, ci, 2 * wc);
        float v1 = fetch_w(wl1, 2072, 256, n, ci, 2 * wc + 1);
        float h0 = __bfloat162float(__float2bfloat16_rn(v0));
        float h1 = __bfloat162float(__float2bfloat16_rn(v1));
        g_B1[i] = h ? pack_bf16(v0 - h0, v1 - h1) : pack_bf16(h0, h1);
    }
    if (i < NCH2 * CHUNK_WORDS) {
        int ci = i / CHUNK_WORDS, r = i % CHUNK_WORDS;
        int h = r / 5120, r2 = r % 5120;
        int n = r2 / ROWW, wc = r2 % ROWW;
        float v0 = fetch_w(wl2, 1048, 128, n, ci, 2 * wc);
        float v1 = fetch_w(wl2, 1048, 128, n, ci, 2 * wc + 1);
        float h0 = __bfloat162float(__float2bfloat16_rn(v0));
        float h1 = __bfloat162float(__float2bfloat16_rn(v1));
        g_B2[i] = h ? pack_bf16(v0 - h0, v1 - h1) : pack_bf16(h0, h1);
    }
}

// ---------------- fused point-conv (mma.sync bf16 3-term) ----------------------
// dyn smem word offsets:
#define OFF_AH 0            // 5120 words (128 rows x 40, bf16x2)
#define OFF_AL 5120
#define OFF_B  10240        // 10240 words ([h][128][40])
#define OFF_W  20480        // s_w fp32 [128][128]
#define OFF_NBR 36864       // 2048 ints
#define OFF_CX 38912        // 384
#define OFF_BIAS 39296      // 128
#define DYN_WORDS 39424
#define DYN_BYTES (DYN_WORDS * 4)

template <int CIN, int STRIDE_IN, int OUT_STRIDE, int NCHUNK>
__global__ void __launch_bounds__(256, 1)
conv_mma(const float* __restrict__ fcat, const int* __restrict__ knn,
         const float* __restrict__ w_wn, const float* __restrict__ b_wn,
         const float* __restrict__ b_lin, const uint32_t* __restrict__ gB,
         float* __restrict__ out) {
    constexpr int CIN3 = CIN + 3;

    extern __shared__ float dyn[];
    uint32_t* sAH = (uint32_t*)dyn + OFF_AH;
    uint32_t* sAL = (uint32_t*)dyn + OFF_AL;
    uint32_t* sB  = (uint32_t*)dyn + OFF_B;
    float* s_w    = dyn + OFF_W;
    int*   s_nbr  = (int*)(dyn + OFF_NBR);
    float* s_cx   = dyn + OFF_CX;
    float* s_bias = dyn + OFF_BIAS;

    __shared__ float s_wn[24];
    __shared__ float s_bwn[8];

    const int tid  = threadIdx.x;
    const int wid  = tid >> 5, lane = tid & 31;
    const int g    = lane >> 2, t = lane & 3;
    const int base = blockIdx.x * 128;
    const int boff = (base >> 13) << 13;

    if (tid < 24) s_wn[tid] = w_wn[tid];
    if (tid < 8)  s_bwn[tid] = b_wn[tid];
    if (tid < 128) {
        s_bias[tid] = b_lin[tid];
        const float* cp = fcat + (size_t)(base + tid) * STRIDE_IN + CIN;
        s_cx[tid * 3 + 0] = cp[0];
        s_cx[tid * 3 + 1] = cp[1];
        s_cx[tid * 3 + 2] = cp[2];
    }
#pragma unroll
    for (int r = 0; r < 8; ++r) {
        int id = tid + r * 256;
        int pt = id >> 4, k = id & 15;
        s_nbr[id] = boff + knn[(size_t)(base + pt) * KNN + k];
    }
    __syncthreads();

    // weight-net into s_w[pt][k*8+m]
#pragma unroll
    for (int r = 0; r < 8; ++r) {
        int id = tid + r * 256;
        int pt = id >> 4, k = id & 15;
        int j = s_nbr[id];
        const float* nx = fcat + (size_t)j * STRIDE_IN + CIN;
        float px = nx[0] - s_cx[pt * 3 + 0];
        float py = nx[1] - s_cx[pt * 3 + 1];
        float pz = nx[2] - s_cx[pt * 3 + 2];
#pragma unroll
        for (int m = 0; m < 8; ++m) {
            float v = s_wn[m * 3 + 0] * px + s_wn[m * 3 + 1] * py +
                      s_wn[m * 3 + 2] * pz + s_bwn[m];
            s_w[pt * 128 + k * 8 + m] = lrelu(v);
        }
    }
    __syncthreads();

    float acc[64];
#pragma unroll
    for (int i = 0; i < 64; ++i) acc[i] = 0.f;

    const int row_g = wid * 16 + g;

    for (int ci = 0; ci < NCHUNK; ++ci) {
        // ---- B chunk copy (pre-split, pre-permuted, pre-padded)
        {
            const uint4* src = (const uint4*)(gB + (size_t)ci * CHUNK_WORDS);
            uint4* dst = (uint4*)sB;
            for (int i2 = tid; i2 < CHUNK_WORDS / 4; i2 += 256) dst[i2] = __ldg(src + i2);
        }

        // ---- A producer: (pt, c) per lane, 4 rounds per warp
        const int c0ch = ci * 8;
#pragma unroll 1
        for (int pb = 0; pb < 4; ++pb) {
            const int pt = wid * 16 + pb * 4 + (lane >> 3);
            const int c  = lane & 7;
            const int cg = c0ch + c;
            const bool valid = (cg < CIN3);
            const int* np_ = s_nbr + pt * 16;
            const float* fp = fcat + cg;
            const ull* wp = (const ull*)(s_w + pt * 128);
            ull a0 = 0, a1 = 0, a2 = 0, a3 = 0;
#pragma unroll
            for (int k = 0; k < 16; ++k) {
                float fv = valid ? __ldg(fp + (size_t)np_[k] * STRIDE_IN) : 0.f;
                ull fd = dup2(fv);
                ulonglong2 w01 = *(const ulonglong2*)(wp + k * 4);
                ulonglong2 w23 = *(const ulonglong2*)(wp + k * 4 + 2);
                a0 = ffma2(fd, w01.x, a0);
                a1 = ffma2(fd, w01.y, a1);
                a2 = ffma2(fd, w23.x, a2);
                a3 = ffma2(fd, w23.y, a3);
            }
            float2 m01 = unpk(a0), m23 = unpk(a1), m45 = unpk(a2), m67 = unpk(a3);
            float v[8] = { m01.x, m01.y, m23.x, m23.y, m45.x, m45.y, m67.x, m67.y };
            float hi[8], lo[8];
#pragma unroll
            for (int q = 0; q < 8; ++q) {
                hi[q] = __bfloat162float(__float2bfloat16_rn(v[q]));
                lo[q] = v[q] - hi[q];
            }
            // storage: word slot = pt*40 + (c>>1)*8 + (c&1); m-pairs at +0,+2,+4,+6
            const int slot = pt * ROWW + ((c >> 1) << 3) + (c & 1);
            sAH[slot + 0] = pack_bf16(hi[0], hi[1]);
            sAH[slot + 2] = pack_bf16(hi[2], hi[3]);
            sAH[slot + 4] = pack_bf16(hi[4], hi[5]);
            sAH[slot + 6] = pack_bf16(hi[6], hi[7]);
            sAL[slot + 0] = pack_bf16(lo[0], lo[1]);
            sAL[slot + 2] = pack_bf16(lo[2], lo[3]);
            sAL[slot + 4] = pack_bf16(lo[4], lo[5]);
            sAL[slot + 6] = pack_bf16(lo[6], lo[7]);
        }
        __syncthreads();

        // ---- MMA: warp computes rows [row_g, row_g+8] x all 128 cols
#pragma unroll
        for (int s = 0; s < 4; ++s) {
            const int off = s * 8 + 2 * t;
            uint2 ah  = *(const uint2*)(sAH + row_g * ROWW + off);        // a0, a2
            uint2 ah8 = *(const uint2*)(sAH + (row_g + 8) * ROWW + off);  // a1, a3
            uint2 al  = *(const uint2*)(sAL + row_g * ROWW + off);
            uint2 al8 = *(const uint2*)(sAL + (row_g + 8) * ROWW + off);
#pragma unroll
            for (int nt = 0; nt < 16; ++nt) {
                uint2 bh = *(const uint2*)(sB + (nt * 8 + g) * ROWW + off);
                uint2 bl = *(const uint2*)(sB + 5120 + (nt * 8 + g) * ROWW + off);
                float* C = acc + nt * 4;
                mma_bf16(C, ah.x, ah8.x, ah.y, ah8.y, bh.x, bh.y);
                mma_bf16(C, ah.x, ah8.x, ah.y, ah8.y, bl.x, bl.y);
                mma_bf16(C, al.x, al8.x, al.y, al8.y, bh.x, bh.y);
            }
        }
        __syncthreads();
    }

    // ---- epilogue: bias + leaky, direct global writes
#pragma unroll
    for (int nt = 0; nt < 16; ++nt) {
        const int col = nt * 8 + 2 * t;
        float b0 = s_bias[col], b1 = s_bias[col + 1];
        float2 r01 = make_float2(lrelu(acc[nt * 4 + 0] + b0), lrelu(acc[nt * 4 + 1] + b1));
        float2 r23 = make_float2(lrelu(acc[nt * 4 + 2] + b0), lrelu(acc[nt * 4 + 3] + b1));
        *(float2*)(out + (size_t)(base + row_g) * OUT_STRIDE + col) = r01;
        *(float2*)(out + (size_t)(base + row_g + 8) * OUT_STRIDE + col) = r23;
    }
}

// ---------------- MLP head ------------------------------------------------------
__global__ void mlp_kernel(const float* __restrict__ w_last, const float* __restrict__ b1,
                           const float* __restrict__ b2, const float* __restrict__ blast,
                           float* __restrict__ out) {
    __shared__ float s_f[16 * 128];
    __shared__ float s_h1[16 * 128];
    __shared__ float s_h2[16 * 64];
    const int tid = threadIdx.x;
    const int p0  = blockIdx.x * 16;

    for (int i = tid; i < 16 * 128; i += 256) s_f[i] = g_f2[(size_t)p0 * 128 + i];
    __syncthreads();
    {
        int o = tid & 127, tg = tid >> 7;
        float acc[8];
#pragma unroll
        for (int i = 0; i < 8; ++i) acc[i] = 0.f;
        for (int c = 0; c < 128; ++c) {
            float wv = g_w1t[c * 128 + o];
#pragma unroll
            for (int i = 0; i < 8; ++i) acc[i] += s_f[(tg * 8 + i) * 128 + c] * wv;
        }
        float bb = b1[o];
#pragma unroll
        for (int i = 0; i < 8; ++i) s_h1[(tg * 8 + i) * 128 + o] = lrelu(acc[i] + bb);
    }
    __syncthreads();
    {
        int jj = tid & 63, tg = tid >> 6;
        float acc[4];
#pragma unroll
        for (int i = 0; i < 4; ++i) acc[i] = 0.f;
        for (int c = 0; c < 128; ++c) {
            float wv = g_w2t[c * 64 + jj];
#pragma unroll
            for (int i = 0; i < 4; ++i) acc[i] += s_h1[(tg * 4 + i) * 128 + c] * wv;
        }
        float bb = b2[jj];
#pragma unroll
        for (int i = 0; i < 4; ++i) s_h2[(tg * 4 + i) * 64 + jj] = lrelu(acc[i] + bb);
    }
    __syncthreads();

    const int b = p0 >> 13, n0 = p0 & (NPTS - 1);
    for (int i = tid; i < 16 * 64; i += 256) {
        int t2 = i & 15, jj = i >> 4;
        out[((size_t)(b * 64 + jj)) * NPTS + n0 + t2] = s_h2[t2 * 64 + jj];
    }
    if (tid < 48) {
        int t2 = tid & 15, d = tid >> 4;
        float acc = 0.f;
#pragma unroll 8
        for (int jj = 0; jj < 64; ++jj) acc += w_last[d * 64 + jj] * s_h2[t2 * 64 + jj];
        out[(size_t)BATCH * 64 * NPTS + ((size_t)(b * 3 + d)) * NPTS + n0 + t2] = acc + blast[d];
    }
}

// ---------------- launch ----------------------------------------------------------
extern "C" void kernel_launch(void* const* d_in, const int* in_sizes, int n_in,
                              void* d_out, int out_size) {
    const float* xyz    = (const float*)d_in[0];
    const float* feat   = (const float*)d_in[1];
    const int*   knn    = (const int*)d_in[2];
    const float* w_wn1  = (const float*)d_in[3];
    const float* b_wn1  = (const float*)d_in[4];
    const float* w_lin1 = (const float*)d_in[5];
    const float* b_lin1 = (const float*)d_in[6];
    const float* w_wn2  = (const float*)d_in[7];
    const float* b_wn2  = (const float*)d_in[8];
    const float* w_lin2 = (const float*)d_in[9];
    const float* b_lin2 = (const float*)d_in[10];
    const float* w_mlp1 = (const float*)d_in[11];
    const float* b_mlp1 = (const float*)d_in[12];
    const float* w_mlp2 = (const float*)d_in[13];
    const float* b_mlp2 = (const float*)d_in[14];
    const float* w_last = (const float*)d_in[15];
    const float* b_last = (const float*)d_in[16];
    float* out = (float*)d_out;

    void *p_fcat1, *p_fcat2, *p_f2, *p_B1, *p_B2;
    cudaGetSymbolAddress(&p_fcat1, g_fcat1);
    cudaGetSymbolAddress(&p_fcat2, g_fcat2);
    cudaGetSymbolAddress(&p_f2, g_f2);
    cudaGetSymbolAddress(&p_B1, g_B1);
    cudaGetSymbolAddress(&p_B2, g_B2);

    prep_weights<<<(128 * 128 + 255) / 256, 256>>>(w_mlp1, w_mlp2);
    prep_xyz<<<(NP_TOTAL * 3 + 255) / 256, 256>>>(xyz);
    prep_B<<<(NCH1 * CHUNK_WORDS + 255) / 256, 256>>>(w_lin1, w_lin2);
    {
        dim3 tb(32, 32);
        dim3 tg(NPTS / 32, 256 / 32, BATCH);
        transpose_feat<<<tg, tb>>>(feat);
    }

    cudaFuncSetAttribute(conv_mma<256, 260, 132, NCH1>,
                         cudaFuncAttributeMaxDynamicSharedMemorySize, DYN_BYTES);
    conv_mma<256, 260, 132, NCH1><<<NP_TOTAL / 128, 256, DYN_BYTES>>>(
        (const float*)p_fcat1, knn, w_wn1, b_wn1, b_lin1, (const uint32_t*)p_B1,
        (float*)p_fcat2);

    cudaFuncSetAttribute(conv_mma<128, 132, 128, NCH2>,
                         cudaFuncAttributeMaxDynamicSharedMemorySize, DYN_BYTES);
    conv_mma<128, 132, 128, NCH2><<<NP_TOTAL / 128, 256, DYN_BYTES>>>(
        (const float*)p_fcat2, knn, w_wn2, b_wn2, b_lin2, (const uint32_t*)p_B2,
        (float*)p_f2);

    mlp_kernel<<<NP_TOTAL / 16, 256>>>(w_last, b_mlp1, b_mlp2, b_last, out);
}